// round 2
// baseline (speedup 1.0000x reference)
#include <cuda_runtime.h>

#define WD    2048
#define BATCH 256
#define NOUT  11
#define YPAD  12
#define PF    4

// Scratch (allocation-guard-safe __device__ globals)
__device__ float g_y[BATCH * WD * YPAD];   // layer-0 output summed over dirs, padded to 12
__device__ float g_xs[BATCH * WD];         // x summed over H

__device__ __forceinline__ float fx_ex2(float x) { float y; asm("ex2.approx.f32 %0, %1;" : "=f"(y) : "f"(x)); return y; }
__device__ __forceinline__ float fx_rcp(float x) { float y; asm("rcp.approx.f32 %0, %1;" : "=f"(y) : "f"(x)); return y; }
__device__ __forceinline__ float sigm(float x)   { return fx_rcp(1.0f + fx_ex2(-1.4426950408889634f * x)); }
__device__ __forceinline__ float tanh_(float x)  { return fmaf(2.0f, sigm(2.0f * x), -1.0f); }

// Sum x over H=32, zero the dir-sum scratch and the output.
__global__ void prep_kernel(const float* __restrict__ x, float* __restrict__ out)
{
    int tid = blockIdx.x * blockDim.x + threadIdx.x;
    int nt  = gridDim.x * blockDim.x;
    for (int i = tid; i < BATCH * WD; i += nt) {
        int b = i >> 11, w = i & (WD - 1);
        const float* p = x + (size_t)b * 32 * WD + w;
        float s = 0.f;
        #pragma unroll
        for (int h = 0; h < 32; h++) s += p[(size_t)h * WD];
        g_xs[i] = s;
    }
    for (int i = tid; i < BATCH * WD * YPAD; i += nt) g_y[i] = 0.f;
    for (int i = tid; i < BATCH * NOUT * WD; i += nt) out[i] = 0.f;
}

// One MDLSTM layer. 2 sequences per warp (lanes 0-15 / 16-31); lane j<11 owns
// output channel j: all 4 live gate columns (i, f_w, o, a) of U and W live in
// registers. h is replicated to all lanes via shfl each step. f_h gate is dead
// (height==1 -> zero vertical cell), so it is skipped entirely.
template<int LAYER>
__global__ void __launch_bounds__(128, 1) mdlstm_kernel(
    const float* __restrict__ Wmat,   // (4, CIN, 55)
    const float* __restrict__ Umat,   // (4, 11, 55)
    const float* __restrict__ bvec,   // (4, 55)
    float* __restrict__ outp)         // layer1: d_out (B,11,WD); layer0 writes g_y
{
    constexpr int CIN = (LAYER == 0) ? 1 : NOUT;

    int warp = (blockIdx.x * blockDim.x + threadIdx.x) >> 5;
    int lane = threadIdx.x & 31;
    int half = lane >> 4;
    int j    = lane & 15;
    int seq  = warp * 2 + half;          // 0..1023
    int d    = seq >> 8;                 // direction 0..3
    int b    = seq & 255;                // batch
    bool fwd    = ((d & 1) == 0);        // dirs 0,2 forward; 1,3 backward
    bool active = (j < NOUT);
    int  jj     = active ? j : 0;
    int  base   = half << 4;

    // Per-lane weight columns: gate offsets i=0, f_w=11, o=33, a=44 (f_h=22 dead)
    const float* Ud = Umat + d * NOUT * 55;
    const float* Wd = Wmat + d * CIN * 55;
    float Ui[NOUT], Uf[NOUT], Uo[NOUT], Ua[NOUT];
    #pragma unroll
    for (int k = 0; k < NOUT; k++) {
        Ui[k] = Ud[k * 55 + 0  + jj];
        Uf[k] = Ud[k * 55 + 11 + jj];
        Uo[k] = Ud[k * 55 + 33 + jj];
        Ua[k] = Ud[k * 55 + 44 + jj];
    }
    float Wi[CIN], Wf[CIN], Wo[CIN], Wa[CIN];
    #pragma unroll
    for (int k = 0; k < CIN; k++) {
        Wi[k] = Wd[k * 55 + 0  + jj];
        Wf[k] = Wd[k * 55 + 11 + jj];
        Wo[k] = Wd[k * 55 + 33 + jj];
        Wa[k] = Wd[k * 55 + 44 + jj];
    }
    float bi = bvec[d * 55 + 0  + jj];
    float bf = bvec[d * 55 + 11 + jj];
    float bo = bvec[d * 55 + 33 + jj];
    float ba = bvec[d * 55 + 44 + jj];

    int stepd = fwd ? 1 : -1;
    int pos0  = fwd ? 0 : WD - 1;

    // Input prefetch ring, depth PF (covers L2 latency).
    // Layer0: every lane loads the scalar xs. Layer1: lane j loads y_j, broadcast later.
    float pin[PF];
    #pragma unroll
    for (int p = 0; p < PF; p++) {
        int pp = pos0 + p * stepd;
        pin[p] = (LAYER == 0) ? g_xs[b * WD + pp]
                              : g_y[(b * WD + pp) * YPAD + jj];
    }

    float ha[NOUT];
    #pragma unroll
    for (int k = 0; k < NOUT; k++) ha[k] = 0.f;
    float c = 0.f;

    int pos = pos0;
    for (int t = 0; t < WD; t += PF) {
        #pragma unroll
        for (int u = 0; u < PF; u++) {
            // --- input projection (independent of h; fills latency gaps) ---
            float gi = bi, gf = bf, go = bo, ga = ba;
            if (LAYER == 0) {
                float xv = pin[u];
                gi = fmaf(xv, Wi[0], gi);
                gf = fmaf(xv, Wf[0], gf);
                go = fmaf(xv, Wo[0], go);
                ga = fmaf(xv, Wa[0], ga);
            } else {
                #pragma unroll
                for (int k = 0; k < NOUT; k++) {
                    float yk = __shfl_sync(0xffffffffu, pin[u], base + k);
                    gi = fmaf(yk, Wi[k], gi);
                    gf = fmaf(yk, Wf[k], gf);
                    go = fmaf(yk, Wo[k], go);
                    ga = fmaf(yk, Wa[k], ga);
                }
            }
            // --- refill prefetch slot for step t+u+PF ---
            {
                int tn = t + u + PF;
                int tc = (tn < WD) ? tn : (WD - 1);
                int pn = pos0 + tc * stepd;
                pin[u] = (LAYER == 0) ? g_xs[b * WD + pn]
                                      : g_y[(b * WD + pn) * YPAD + jj];
            }
            // --- recurrent matvec (the serial chain) ---
            #pragma unroll
            for (int k = 0; k < NOUT; k++) {
                gi = fmaf(ha[k], Ui[k], gi);
                gf = fmaf(ha[k], Uf[k], gf);
                go = fmaf(ha[k], Uo[k], go);
                ga = fmaf(ha[k], Ua[k], ga);
            }
            float iv = sigm(gi);
            float fv = sigm(gf);
            float ov = sigm(go);
            float av = tanh_(ga);
            c = fmaf(fv, c, iv * av);
            float h = ov * tanh_(c);

            // --- accumulate over directions ---
            if (active) {
                if (LAYER == 0)
                    atomicAdd(&g_y[(b * WD + pos) * YPAD + jj], h);
                else
                    atomicAdd(&outp[(b * NOUT + jj) * WD + pos], h);
            }
            // --- replicate h to all lanes of this half-warp ---
            #pragma unroll
            for (int k = 0; k < NOUT; k++)
                ha[k] = __shfl_sync(0xffffffffu, h, base + k);

            pos += stepd;
        }
    }
}

extern "C" void kernel_launch(void* const* d_in, const int* in_sizes, int n_in,
                              void* d_out, int out_size)
{
    const float* x  = (const float*)d_in[0];
    const float* W0 = (const float*)d_in[1];
    const float* U0 = (const float*)d_in[2];
    const float* b0 = (const float*)d_in[3];
    const float* W1 = (const float*)d_in[4];
    const float* U1 = (const float*)d_in[5];
    const float* b1 = (const float*)d_in[6];
    float* out = (float*)d_out;

    prep_kernel<<<1024, 256>>>(x, out);
    // 1024 sequences, 2 per warp, 4 warps per block -> 128 blocks
    mdlstm_kernel<0><<<128, 128>>>(W0, U0, b0, out);
    mdlstm_kernel<1><<<128, 128>>>(W1, U1, b1, out);
}

// round 7
// speedup vs baseline: 1.0043x; 1.0043x over previous
#include <cuda_runtime.h>

#define WD    2048
#define BATCH 256
#define NOUT  11
#define YPAD  12
#define PF    4

typedef unsigned long long u64t;

// Scratch (allocation-guard-safe __device__ globals)
__device__ float g_y[BATCH * WD * YPAD];   // layer-0 output summed over dirs (padded to 12)
__device__ float g_xs[BATCH * WD];         // x summed over H

__device__ __forceinline__ float fx_ex2(float x){ float y; asm("ex2.approx.f32 %0, %1;" : "=f"(y) : "f"(x)); return y; }
__device__ __forceinline__ float fx_rcp(float x){ float y; asm("rcp.approx.f32 %0, %1;" : "=f"(y) : "f"(x)); return y; }

// packed f32x2 helpers (sm_103a FFMA2 path)
__device__ __forceinline__ u64t pack2(float lo, float hi){ u64t r; asm("mov.b64 %0, {%1,%2};" : "=l"(r) : "f"(lo), "f"(hi)); return r; }
__device__ __forceinline__ void unpack2(u64t v, float& lo, float& hi){ asm("mov.b64 {%0,%1}, %2;" : "=f"(lo), "=f"(hi) : "l"(v)); }
__device__ __forceinline__ u64t fma2_(u64t a, u64t b, u64t c){ u64t d; asm("fma.rn.f32x2 %0, %1, %2, %3;" : "=l"(d) : "l"(a), "l"(b), "l"(c)); return d; }
__device__ __forceinline__ u64t add2_(u64t a, u64t b){ u64t d; asm("add.rn.f32x2 %0, %1, %2;" : "=l"(d) : "l"(a), "l"(b)); return d; }

// Sum x over H=32 (vectorized), zero the dir-sum scratch and the output.
__global__ void prep_kernel(const float* __restrict__ x, float* __restrict__ out)
{
    int tid = blockIdx.x * blockDim.x + threadIdx.x;
    int nt  = gridDim.x * blockDim.x;
    const int NXS4 = BATCH * WD / 4;
    for (int i = tid; i < NXS4; i += nt) {
        int b  = i >> 9;          // WD/4 = 512 vectors per batch row
        int w4 = i & 511;
        const float4* p = reinterpret_cast<const float4*>(x + (size_t)b * 32 * WD) + w4;
        float4 s = make_float4(0.f, 0.f, 0.f, 0.f);
        #pragma unroll
        for (int h = 0; h < 32; h++) {
            float4 v = p[h * (WD / 4)];
            s.x += v.x; s.y += v.y; s.z += v.z; s.w += v.w;
        }
        reinterpret_cast<float4*>(g_xs)[i] = s;
    }
    float4 z = make_float4(0.f, 0.f, 0.f, 0.f);
    for (int i = tid; i < BATCH * WD * YPAD / 4; i += nt) reinterpret_cast<float4*>(g_y)[i] = z;
    for (int i = tid; i < BATCH * NOUT * WD / 4; i += nt) reinterpret_cast<float4*>(out)[i] = z;
}

// One MDLSTM layer. 2 sequences per warp (lanes 0-15 / 16-31); lane j<11 owns
// channel j with all 4 live gate columns (i,f_w,o,a) in registers, pre-scaled
// by -log2(e) (sigmoid gates) / -2log2(e) (tanh gate) so nonlinearities need
// no dependent multiply. f_h gate is dead (height==1). Gate pairs (i,f),(o,a)
// are evaluated with packed fma.rn.f32x2; the recurrent dot uses 3 accumulators
// to cut the serial FMA chain from 44 to ~24 cycles.
template<int LAYER>
__global__ void __launch_bounds__(128, 1) mdlstm_kernel(
    const float* __restrict__ Wmat,   // (4, CIN, 55)
    const float* __restrict__ Umat,   // (4, 11, 55)
    const float* __restrict__ bvec,   // (4, 55)
    float* __restrict__ outp)         // layer1: d_out (B,11,WD); layer0 -> g_y
{
    constexpr int CIN = (LAYER == 0) ? 1 : NOUT;
    const float SS = -1.4426950408889634f;   // -log2(e)
    const float ST = -2.8853900817779268f;   // -2*log2(e)

    int warp = (blockIdx.x * blockDim.x + threadIdx.x) >> 5;
    int lane = threadIdx.x & 31;
    int half = lane >> 4;
    int j    = lane & 15;
    int seq  = warp * 2 + half;          // 0..1023
    int d    = seq >> 8;                 // direction
    int b    = seq & 255;                // batch
    bool fwd    = ((d & 1) == 0);
    bool active = (j < NOUT);
    int  jj     = active ? j : 0;
    int  base   = half << 4;

    const float* Ud = Umat + d * NOUT * 55;
    const float* Wd = Wmat + d * CIN * 55;
    const float* bd = bvec + d * 55;

    u64t Uif[NOUT], Uoa[NOUT];
    #pragma unroll
    for (int k = 0; k < NOUT; k++) {
        Uif[k] = pack2(Ud[k*55 + 0  + jj] * SS, Ud[k*55 + 11 + jj] * SS);
        Uoa[k] = pack2(Ud[k*55 + 33 + jj] * SS, Ud[k*55 + 44 + jj] * ST);
    }
    u64t Wif[CIN], Woa[CIN];
    #pragma unroll
    for (int k = 0; k < CIN; k++) {
        Wif[k] = pack2(Wd[k*55 + 0  + jj] * SS, Wd[k*55 + 11 + jj] * SS);
        Woa[k] = pack2(Wd[k*55 + 33 + jj] * SS, Wd[k*55 + 44 + jj] * ST);
    }
    u64t bif = pack2(bd[0 + jj] * SS, bd[11 + jj] * SS);
    u64t boa = pack2(bd[33 + jj] * SS, bd[44 + jj] * ST);

    int stepd = fwd ? 1 : -1;
    int pos0  = fwd ? 0 : WD - 1;

    // Input prefetch ring, depth PF (covers L2/DRAM latency; off the chain).
    float pin[PF];
    #pragma unroll
    for (int p = 0; p < PF; p++) {
        int pp = pos0 + p * stepd;
        pin[p] = (LAYER == 0) ? g_xs[b * WD + pp]
                              : g_y[(b * WD + pp) * YPAD + jj];
    }

    u64t ha2[NOUT];
    #pragma unroll
    for (int k = 0; k < NOUT; k++) ha2[k] = 0ull;
    float c = 0.f;

    int pos = pos0;
    for (int t = 0; t < WD; t += PF) {
        #pragma unroll
        for (int u = 0; u < PF; u++) {
            // --- input projection (independent of h; hides in chain stalls) ---
            u64t aif = bif, aoa = boa;
            if (LAYER == 0) {
                u64t xv2 = pack2(pin[u], pin[u]);
                aif = fma2_(xv2, Wif[0], aif);
                aoa = fma2_(xv2, Woa[0], aoa);
            } else {
                #pragma unroll
                for (int k = 0; k < NOUT; k++) {
                    float yk = __shfl_sync(0xffffffffu, pin[u], base + k);
                    u64t y2 = pack2(yk, yk);
                    aif = fma2_(y2, Wif[k], aif);
                    aoa = fma2_(y2, Woa[k], aoa);
                }
            }
            // --- refill prefetch slot for step t+u+PF ---
            {
                int tn = t + u + PF;
                int tc = (tn < WD) ? tn : (WD - 1);
                int pn = pos0 + tc * stepd;
                pin[u] = (LAYER == 0) ? g_xs[b * WD + pn]
                                      : g_y[(b * WD + pn) * YPAD + jj];
            }
            // --- recurrent matvec: 3 accumulators per gate pair (short chain) ---
            u64t p0 = 0ull, p1 = 0ull, p2 = 0ull;
            u64t q0 = 0ull, q1 = 0ull, q2 = 0ull;
            #pragma unroll
            for (int k = 0; k < NOUT; k += 3) {
                p0 = fma2_(ha2[k], Uif[k], p0);
                q0 = fma2_(ha2[k], Uoa[k], q0);
                if (k + 1 < NOUT) {
                    p1 = fma2_(ha2[k+1], Uif[k+1], p1);
                    q1 = fma2_(ha2[k+1], Uoa[k+1], q1);
                }
                if (k + 2 < NOUT) {
                    p2 = fma2_(ha2[k+2], Uif[k+2], p2);
                    q2 = fma2_(ha2[k+2], Uoa[k+2], q2);
                }
            }
            u64t gif = add2_(add2_(p0, p1), add2_(p2, aif));
            u64t goa = add2_(add2_(q0, q1), add2_(q2, aoa));

            float gi, gf, go, ga;
            unpack2(gif, gi, gf);
            unpack2(goa, go, ga);
            // gates pre-scaled: sigmoid(x) = rcp(1+ex2(SS*x)), tanh(x) = 2*rcp(1+ex2(ST*x))-1
            float iv = fx_rcp(1.f + fx_ex2(gi));
            float fv = fx_rcp(1.f + fx_ex2(gf));
            float ov = fx_rcp(1.f + fx_ex2(go));
            float av = fmaf(2.f, fx_rcp(1.f + fx_ex2(ga)), -1.f);
            c = fmaf(fv, c, iv * av);
            float th = fmaf(2.f, fx_rcp(1.f + fx_ex2(ST * c)), -1.f);
            float h = ov * th;

            // --- accumulate over directions (REDG, off the chain) ---
            if (active) {
                if (LAYER == 0)
                    atomicAdd(&g_y[(b * WD + pos) * YPAD + jj], h);
                else
                    atomicAdd(&outp[(b * NOUT + jj) * WD + pos], h);
            }
            // --- replicate h to all lanes of this half-warp, pre-packed ---
            #pragma unroll
            for (int k = 0; k < NOUT; k++) {
                float hk = __shfl_sync(0xffffffffu, h, base + k);
                ha2[k] = pack2(hk, hk);
            }

            pos += stepd;
        }
    }
}

extern "C" void kernel_launch(void* const* d_in, const int* in_sizes, int n_in,
                              void* d_out, int out_size)
{
    const float* x  = (const float*)d_in[0];
    const float* W0 = (const float*)d_in[1];
    const float* U0 = (const float*)d_in[2];
    const float* b0 = (const float*)d_in[3];
    const float* W1 = (const float*)d_in[4];
    const float* U1 = (const float*)d_in[5];
    const float* b1 = (const float*)d_in[6];
    float* out = (float*)d_out;

    prep_kernel<<<1024, 256>>>(x, out);
    // 1024 sequences, 2 per warp, 4 warps per block -> 128 blocks
    mdlstm_kernel<0><<<128, 128>>>(W0, U0, b0, out);
    mdlstm_kernel<1><<<128, 128>>>(W1, U1, b1, out);
}